// round 11
// baseline (speedup 1.0000x reference)
#include <cuda_runtime.h>
#include <cuda_fp16.h>
#include <math.h>

// ---------------------------------------------------------------------------
// TOF PET forward projection.
//  Pass 1: smem-tiled build of corner-packed fp16 image, row-major AND
//          transposed layouts (image only — no event params).
//  Pass 2: 8 threads/event; lanes 0-3 of each warp compute the 4 events'
//          parameters cooperatively, shfl-broadcast to octets, then the
//          strength-reduced sampling loop on the layout's fast axis.
// ---------------------------------------------------------------------------

#define PAD_W   384            // stride (entries) for BOTH layouts
#define PADX    40
#define PADY    40
#define NSAMP   256
#define INV_NSAMP (1.0f / 256.0f)
#define ZCUT    3.6f           // Gaussian truncation: tail 2*Q(3.6) ~ 3.2e-4
#define SPLIT   8              // threads per event
#define NTILE   18             // 18x18 tiles of 16 cover ix,iy in [-1, 286]

// 8-byte corner pack for entry[v][u]:
//   lo = (c00, c10) = (val(u,v),   val(u,v+1))
//   hi = (c01, c11) = (val(u+1,v), val(u+1,v+1))
struct __align__(8) h4 { __half2 lo, hi; };

// Zero-initialized; pad borders stay zero (outside-image masking).
__device__ h4 g_padh [PAD_W * PAD_W];   // (u,v) = (x,y)
__device__ h4 g_padhT[PAD_W * PAD_W];   // (u,v) = (y,x)

__global__ void prep_kernel(const float* __restrict__ img,
                            const int* __restrict__ nxp,
                            const int* __restrict__ nyp)
{
    const int nx = *nxp;
    const int ny = *nyp;
    const int tid = threadIdx.x;
    const int blk = blockIdx.x;

    __shared__ float sm[17][18];
    const int ty = blk / NTILE;
    const int tx = blk - ty * NTILE;
    const int ixs = -1 + tx * 16;          // tile origin in image coords
    const int iys = -1 + ty * 16;

    for (int k = tid; k < 17 * 17; k += 256) {
        const int r = k / 17;
        const int c = k - r * 17;
        const int y = iys + r;
        const int x = ixs + c;
        sm[r][c] = (x >= 0 && x < nx && y >= 0 && y < ny)
                   ? img[y * nx + x] : 0.0f;
    }
    __syncthreads();

    // Row-major output: fast axis = x (coalesced 8B stores).
    {
        const int ly = tid >> 4;           // 0..15
        const int lx = tid & 15;
        h4 o;
        o.lo = __floats2half2_rn(sm[ly][lx],     sm[ly + 1][lx]);
        o.hi = __floats2half2_rn(sm[ly][lx + 1], sm[ly + 1][lx + 1]);
        g_padh[(iys + ly + PADY) * PAD_W + (ixs + lx + PADX)] = o;
    }
    // Transposed output: fast axis = y (coalesced 8B stores).
    {
        const int lx = tid >> 4;           // slow: x
        const int ly = tid & 15;           // fast: y
        h4 o;                               // (u,v) = (y,x)
        o.lo = __floats2half2_rn(sm[ly][lx],     sm[ly][lx + 1]);
        o.hi = __floats2half2_rn(sm[ly + 1][lx], sm[ly + 1][lx + 1]);
        g_padhT[(ixs + lx + PADX) * PAD_W + (iys + ly + PADY)] = o;
    }
}

__global__ void __launch_bounds__(128)
project_kernel(const float* __restrict__ tof,
               const float* __restrict__ x1l, const float* __restrict__ y1l,
               const float* __restrict__ x1r, const float* __restrict__ y1r,
               const float* __restrict__ x2l, const float* __restrict__ y2l,
               const float* __restrict__ x2r, const float* __restrict__ y2r,
               const float* __restrict__ trp,
               const float* __restrict__ dxp, const float* __restrict__ dyp,
               const int* __restrict__ nxp, const int* __restrict__ nyp,
               float* __restrict__ out, int E)
{
    const int g     = blockIdx.x * blockDim.x + threadIdx.x;
    const int lane  = threadIdx.x & 31;
    const int oct   = lane >> 3;          // which of the warp's 4 events
    const int h     = lane & 7;           // sample phase within the event
    const int wbase = (g >> 5) << 2;      // first event of this warp
    const int e     = wbase + oct;        // == g >> 3
    const bool valid = (e < E);

    // ---- warp-cooperative per-event parameter computation (lanes 0-3) ----
    float a0 = 0.f, da = 0.f, b0 = 0.f, db = 0.f;
    float z0f = 0.f, dzf = 1.f, scalef = 0.f, pkf = 0.f;

    if (lane < 4) {
        int ev = wbase + lane;
        if (ev >= E) ev = E - 1;

        const float dx = *dxp;
        const float dy = *dyp;
        const float nxf = (float)(*nxp);
        const float nyf = (float)(*nyp);

        const float p1x = 0.5f * (x1l[ev] + x1r[ev]);
        const float p1y = 0.5f * (y1l[ev] + y1r[ev]);
        const float p2x = 0.5f * (x2l[ev] + x2r[ev]);
        const float p2y = 0.5f * (y2l[ev] + y2r[ev]);
        const float dvx = p2x - p1x;
        const float dvy = p2y - p1y;
        const float L   = sqrtf(dvx * dvx + dvy * dvy);

        const float sigma     = (*trp) * 0.3f / (2.0f * 2.3548200450309493f);
        const float inv_sigma = 1.0f / sigma;
        const float norm      = 0.3989422804014327f * inv_sigma;
        const float tc        = 0.5f * L + 0.5f * tof[ev];
        const float step      = L * INV_NSAMP;

        const float dfx = dvx * INV_NSAMP / dx;
        const float dfy = dvy * INV_NSAMP / dy;
        const float fx0 = (p1x + dvx * (0.5f * INV_NSAMP)) / dx + 0.5f * nxf - 0.5f;
        const float fy0 = (p1y + dvy * (0.5f * INV_NSAMP)) / dy + 0.5f * nyf - 0.5f;
        const float dz  = step * inv_sigma;          // > 0 (L > 0)
        const float z0  = (step * 0.5f - tc) * inv_sigma;

        int i_lo = (int)floorf((-ZCUT - z0) / dz);
        int i_hi = (int)ceilf (( ZCUT - z0) / dz);
        if (i_lo < 0)         i_lo = 0;
        if (i_lo > NSAMP - 1) i_lo = NSAMP - 1;
        if (i_hi < 0)         i_hi = 0;
        if (i_hi > NSAMP - 1) i_hi = NSAMP - 1;

        const bool steep = fabsf(dvy) > fabsf(dvx);
        a0 = (steep ? fy0 : fx0) + (float)PADX;
        da = steep ? dfy : dfx;
        b0 = (steep ? fx0 : fy0) + (float)PADY;
        db = steep ? dfx : dfy;
        z0f = z0; dzf = dz; scalef = norm * step;
        pkf = __uint_as_float((unsigned)i_lo | ((unsigned)i_hi << 8) |
                              (steep ? 0x80000000u : 0u));
    }

    // Broadcast event-oct params from lane 'oct' (0..3) to all its lanes.
    const unsigned FULL = 0xffffffffu;
    a0     = __shfl_sync(FULL, a0,     oct);
    da     = __shfl_sync(FULL, da,     oct);
    b0     = __shfl_sync(FULL, b0,     oct);
    db     = __shfl_sync(FULL, db,     oct);
    z0f    = __shfl_sync(FULL, z0f,    oct);
    const float dz = __shfl_sync(FULL, dzf, oct);
    scalef = __shfl_sync(FULL, scalef, oct);
    pkf    = __shfl_sync(FULL, pkf,    oct);

    const unsigned packed = __float_as_uint(pkf);
    const int  i_lo  = (int)(packed & 0xffu);
    const int  i_hi  = (int)((packed >> 8) & 0xffu);
    const bool steep = (packed & 0x80000000u) != 0u;

    const h4* __restrict__ base = steep ? g_padhT : g_padh;

    const float kexp = -0.72134752044448f;     // -0.5 * log2(e)

    // Per-lane initial sample and incremental state (stride 8 in i):
    //   q = kexp * z^2 via second-difference recurrence.
    const int   i0  = i_lo + h;
    const float fi0 = (float)i0;
    float u = fmaf(fi0, da, a0);
    float v = fmaf(fi0, db, b0);
    const float zs = fmaf(fi0, dz, z0f);
    const float kd = kexp * dz;
    float q   = (kexp * zs) * zs;
    float dq  = kd * fmaf(64.0f, dz, 16.0f * zs);   // kexp*(16*dz*zs + 64*dz^2)
    const float ddq = 128.0f * kd * dz;
    const float du = 8.0f * da;
    const float dv = 8.0f * db;

    const int n = (i_hi - i0 >= 0) ? ((i_hi - i0) >> 3) + 1 : 0;

    float acc = 0.0f;

    #pragma unroll 4
    for (int it = 0; it < n; ++it) {
        const int iu = (int)u;            // u,v > 0: trunc == floor
        const int iv = (int)v;
        const float wu = u - (float)iu;
        const float wv = v - (float)iv;

        const h4 c = base[iv * PAD_W + iu];

        const __half2 wu2 = __floats2half2_rn(wu, wu);
        const __half2 l2  = __hfma2(wu2, __hsub2(c.hi, c.lo), c.lo);

        const float l0 = __low2float(l2);
        const float l1 = __high2float(l2);
        const float val = fmaf(wv, l1 - l0, l0);

        float w;
        asm("ex2.approx.ftz.f32 %0, %1;" : "=f"(w) : "f"(q));
        acc = fmaf(w, val, acc);

        u += du; v += dv;
        q += dq; dq += ddq;
    }

    acc += __shfl_xor_sync(FULL, acc, 1);
    acc += __shfl_xor_sync(FULL, acc, 2);
    acc += __shfl_xor_sync(FULL, acc, 4);

    if (valid && h == 0)
        out[e] = acc * scalef;
}

extern "C" void kernel_launch(void* const* d_in, const int* in_sizes, int n_in,
                              void* d_out, int out_size)
{
    const float* image = (const float*)d_in[0];
    const float* tof   = (const float*)d_in[1];
    const float* x1l   = (const float*)d_in[2];
    const float* y1l   = (const float*)d_in[3];
    const float* x1r   = (const float*)d_in[4];
    const float* y1r   = (const float*)d_in[5];
    const float* x2l   = (const float*)d_in[6];
    const float* y2l   = (const float*)d_in[7];
    const float* x2r   = (const float*)d_in[8];
    const float* y2r   = (const float*)d_in[9];
    const float* trp   = (const float*)d_in[10];
    const float* dxp   = (const float*)d_in[11];
    const float* dyp   = (const float*)d_in[12];
    const int*   nxp   = (const int*)d_in[13];
    const int*   nyp   = (const int*)d_in[14];

    const int E = in_sizes[1];

    prep_kernel<<<NTILE * NTILE, 256>>>(image, nxp, nyp);

    const int threads = 128;
    const long long total = (long long)E * SPLIT;
    const int blocks = (int)((total + threads - 1) / threads);
    project_kernel<<<blocks, threads>>>(tof, x1l, y1l, x1r, y1r,
                                        x2l, y2l, x2r, y2r,
                                        trp, dxp, dyp, nxp, nyp,
                                        (float*)d_out, E);
}

// round 13
// speedup vs baseline: 1.0780x; 1.0780x over previous
#include <cuda_runtime.h>
#include <cuda_fp16.h>
#include <math.h>

// ---------------------------------------------------------------------------
// TOF PET forward projection.
//  Pass 1 (prep): smem-tiled build of corner-packed fp16 image, row-major AND
//          transposed layouts. Fires launch_dependents at entry (PDL).
//  Pass 2 (project, PDL secondary): 8 threads/event. Per-thread parameter
//          computation from raw inputs runs BEFORE griddepcontrol.wait, i.e.
//          overlapped with prep; then the strength-reduced sampling loop.
// ---------------------------------------------------------------------------

#define PAD_W   384            // stride (entries) for BOTH layouts
#define PADX    40
#define PADY    40
#define NSAMP   256
#define INV_NSAMP (1.0f / 256.0f)
#define ZCUT    3.6f           // Gaussian truncation: tail 2*Q(3.6) ~ 3.2e-4
#define SPLIT   8              // threads per event
#define NTILE   18             // 18x18 tiles of 16 cover ix,iy in [-1, 286]

// 8-byte corner pack for entry[v][u]:
//   lo = (c00, c10) = (val(u,v),   val(u,v+1))
//   hi = (c01, c11) = (val(u+1,v), val(u+1,v+1))
struct __align__(8) h4 { __half2 lo, hi; };

// Zero-initialized; pad borders stay zero (outside-image masking).
__device__ h4 g_padh [PAD_W * PAD_W];   // (u,v) = (x,y)
__device__ h4 g_padhT[PAD_W * PAD_W];   // (u,v) = (y,x)

__global__ void prep_kernel(const float* __restrict__ img,
                            const int* __restrict__ nxp,
                            const int* __restrict__ nyp)
{
    // Let the dependent (project) launch immediately; its pre-wait phase
    // (event parameter computation) overlaps with this kernel.
    asm volatile("griddepcontrol.launch_dependents;");

    const int nx = *nxp;
    const int ny = *nyp;
    const int tid = threadIdx.x;
    const int blk = blockIdx.x;

    __shared__ float sm[17][18];
    const int ty = blk / NTILE;
    const int tx = blk - ty * NTILE;
    const int ixs = -1 + tx * 16;          // tile origin in image coords
    const int iys = -1 + ty * 16;

    for (int k = tid; k < 17 * 17; k += 256) {
        const int r = k / 17;
        const int c = k - r * 17;
        const int y = iys + r;
        const int x = ixs + c;
        sm[r][c] = (x >= 0 && x < nx && y >= 0 && y < ny)
                   ? img[y * nx + x] : 0.0f;
    }
    __syncthreads();

    // Row-major output: fast axis = x (coalesced 8B stores).
    {
        const int ly = tid >> 4;           // 0..15
        const int lx = tid & 15;
        h4 o;
        o.lo = __floats2half2_rn(sm[ly][lx],     sm[ly + 1][lx]);
        o.hi = __floats2half2_rn(sm[ly][lx + 1], sm[ly + 1][lx + 1]);
        g_padh[(iys + ly + PADY) * PAD_W + (ixs + lx + PADX)] = o;
    }
    // Transposed output: fast axis = y (coalesced 8B stores).
    {
        const int lx = tid >> 4;           // slow: x
        const int ly = tid & 15;           // fast: y
        h4 o;                               // (u,v) = (y,x)
        o.lo = __floats2half2_rn(sm[ly][lx],     sm[ly][lx + 1]);
        o.hi = __floats2half2_rn(sm[ly + 1][lx], sm[ly + 1][lx + 1]);
        g_padhT[(ixs + lx + PADX) * PAD_W + (iys + ly + PADY)] = o;
    }
}

__global__ void __launch_bounds__(128)
project_kernel(const float* __restrict__ tof,
               const float* __restrict__ x1l, const float* __restrict__ y1l,
               const float* __restrict__ x1r, const float* __restrict__ y1r,
               const float* __restrict__ x2l, const float* __restrict__ y2l,
               const float* __restrict__ x2r, const float* __restrict__ y2r,
               const float* __restrict__ trp,
               const float* __restrict__ dxp, const float* __restrict__ dyp,
               const int* __restrict__ nxp, const int* __restrict__ nyp,
               float* __restrict__ out, int E)
{
    const int g = blockIdx.x * blockDim.x + threadIdx.x;
    int       e = g >> 3;                 // event index
    const int h = g & 7;                  // sample phase
    const bool valid = (e < E);
    if (!valid) e = E - 1;

    // ---- per-thread event parameters (raw inputs; overlapped with prep) ----
    const float dx = *dxp;
    const float dy = *dyp;
    const float nxf = (float)(*nxp);
    const float nyf = (float)(*nyp);

    const float p1x = 0.5f * (x1l[e] + x1r[e]);
    const float p1y = 0.5f * (y1l[e] + y1r[e]);
    const float p2x = 0.5f * (x2l[e] + x2r[e]);
    const float p2y = 0.5f * (y2l[e] + y2r[e]);
    const float dvx = p2x - p1x;
    const float dvy = p2y - p1y;
    const float L   = sqrtf(dvx * dvx + dvy * dvy);

    const float sigma     = (*trp) * 0.3f / (2.0f * 2.3548200450309493f);
    const float inv_sigma = 1.0f / sigma;
    const float norm      = 0.3989422804014327f * inv_sigma;
    const float tc        = 0.5f * L + 0.5f * tof[e];
    const float step      = L * INV_NSAMP;

    const float dfx = dvx * INV_NSAMP / dx;
    const float dfy = dvy * INV_NSAMP / dy;
    const float fx0 = (p1x + dvx * (0.5f * INV_NSAMP)) / dx + 0.5f * nxf - 0.5f;
    const float fy0 = (p1y + dvy * (0.5f * INV_NSAMP)) / dy + 0.5f * nyf - 0.5f;
    const float dz  = step * inv_sigma;          // > 0 (L > 0)
    const float z0  = (step * 0.5f - tc) * inv_sigma;

    int i_lo = (int)floorf((-ZCUT - z0) / dz);
    int i_hi = (int)ceilf (( ZCUT - z0) / dz);
    if (i_lo < 0)         i_lo = 0;
    if (i_lo > NSAMP - 1) i_lo = NSAMP - 1;
    if (i_hi < 0)         i_hi = 0;
    if (i_hi > NSAMP - 1) i_hi = NSAMP - 1;

    const bool steep = fabsf(dvy) > fabsf(dvx);
    const float a0 = (steep ? fy0 : fx0) + (float)PADX;
    const float da = steep ? dfy : dfx;
    const float b0 = (steep ? fx0 : fy0) + (float)PADY;
    const float db = steep ? dfx : dfy;

    const h4* __restrict__ base = steep ? g_padhT : g_padh;

    const float kexp = -0.72134752044448f;     // -0.5 * log2(e)

    // Per-lane initial sample and incremental state (stride 8 in i).
    const int   i0  = i_lo + h;
    const float fi0 = (float)i0;
    float u = fmaf(fi0, da, a0);
    float v = fmaf(fi0, db, b0);
    const float zs = fmaf(fi0, dz, z0);
    const float kd = kexp * dz;
    float q   = (kexp * zs) * zs;
    float dq  = kd * fmaf(64.0f, dz, 16.0f * zs);   // kexp*(16*dz*zs + 64*dz^2)
    const float ddq = 128.0f * kd * dz;
    const float du = 8.0f * da;
    const float dv = 8.0f * db;

    const int n = (i_hi - i0 >= 0) ? ((i_hi - i0) >> 3) + 1 : 0;

    // Wait for prep's image-layout writes to be visible.
    asm volatile("griddepcontrol.wait;" ::: "memory");

    float acc = 0.0f;

    #pragma unroll 4
    for (int it = 0; it < n; ++it) {
        const int iu = (int)u;            // u,v > 0: trunc == floor
        const int iv = (int)v;
        const float wu = u - (float)iu;
        const float wv = v - (float)iv;

        const h4 c = base[iv * PAD_W + iu];

        const __half2 wu2 = __floats2half2_rn(wu, wu);
        const __half2 l2  = __hfma2(wu2, __hsub2(c.hi, c.lo), c.lo);

        const float l0 = __low2float(l2);
        const float l1 = __high2float(l2);
        const float val = fmaf(wv, l1 - l0, l0);

        float w;
        asm("ex2.approx.ftz.f32 %0, %1;" : "=f"(w) : "f"(q));
        acc = fmaf(w, val, acc);

        u += du; v += dv;
        q += dq; dq += ddq;
    }

    acc += __shfl_xor_sync(0xffffffffu, acc, 1);
    acc += __shfl_xor_sync(0xffffffffu, acc, 2);
    acc += __shfl_xor_sync(0xffffffffu, acc, 4);

    if (valid && h == 0)
        out[e] = acc * norm * step;
}

extern "C" void kernel_launch(void* const* d_in, const int* in_sizes, int n_in,
                              void* d_out, int out_size)
{
    const float* image = (const float*)d_in[0];
    const float* tof   = (const float*)d_in[1];
    const float* x1l   = (const float*)d_in[2];
    const float* y1l   = (const float*)d_in[3];
    const float* x1r   = (const float*)d_in[4];
    const float* y1r   = (const float*)d_in[5];
    const float* x2l   = (const float*)d_in[6];
    const float* y2l   = (const float*)d_in[7];
    const float* x2r   = (const float*)d_in[8];
    const float* y2r   = (const float*)d_in[9];
    const float* trp   = (const float*)d_in[10];
    const float* dxp   = (const float*)d_in[11];
    const float* dyp   = (const float*)d_in[12];
    const int*   nxp   = (const int*)d_in[13];
    const int*   nyp   = (const int*)d_in[14];

    const int E = in_sizes[1];

    prep_kernel<<<NTILE * NTILE, 256>>>(image, nxp, nyp);

    const int threads = 128;
    const long long total = (long long)E * SPLIT;
    const int blocks = (int)((total + threads - 1) / threads);

    // Launch project as a PDL secondary: it may start while prep runs; its
    // pre-wait phase (parameter computation) overlaps prep's tile writes.
    cudaLaunchConfig_t cfg = {};
    cfg.gridDim  = dim3((unsigned)blocks, 1, 1);
    cfg.blockDim = dim3((unsigned)threads, 1, 1);
    cfg.dynamicSmemBytes = 0;
    cfg.stream = 0;                        // same (capture) stream as prep

    cudaLaunchAttribute attr[1];
    attr[0].id = cudaLaunchAttributeProgrammaticStreamSerialization;
    attr[0].val.programmaticStreamSerializationAllowed = 1;
    cfg.attrs = attr;
    cfg.numAttrs = 1;

    cudaLaunchKernelEx(&cfg, project_kernel,
                       tof, x1l, y1l, x1r, y1r,
                       x2l, y2l, x2r, y2r,
                       trp, dxp, dyp, nxp, nyp,
                       (float*)d_out, E);
}

// round 14
// speedup vs baseline: 1.1860x; 1.1001x over previous
#include <cuda_runtime.h>
#include <cuda_fp16.h>
#include <math.h>

// ---------------------------------------------------------------------------
// TOF PET forward projection.
//  Pass 1 (prep, PDL primary): smem-tiled build of corner-packed fp16 image
//          (row-major AND transposed) + per-event parameters at 1 thread/event.
//  Pass 2 (project, PDL secondary): griddepcontrol.wait at entry, then the
//          proven 8-threads/event strength-reduced loop (R8 configuration).
// ---------------------------------------------------------------------------

#define PAD_W   384            // stride (entries) for BOTH layouts
#define PADX    40
#define PADY    40
#define NSAMP   256
#define INV_NSAMP (1.0f / 256.0f)
#define ZCUT    3.6f           // Gaussian truncation: tail 2*Q(3.6) ~ 3.2e-4
#define SPLIT   8              // threads per event
#define EMAX    160000
#define NTILE   18             // 18x18 tiles of 16 cover ix,iy in [-1, 286]

// 8-byte corner pack for entry[v][u]:
//   lo = (c00, c10) = (val(u,v),   val(u,v+1))
//   hi = (c01, c11) = (val(u+1,v), val(u+1,v+1))
struct __align__(8) h4 { __half2 lo, hi; };

// Zero-initialized; pad borders stay zero (outside-image masking).
__device__ h4 g_padh [PAD_W * PAD_W];   // (u,v) = (x,y)
__device__ h4 g_padhT[PAD_W * PAD_W];   // (u,v) = (y,x)

// Per-event parameters.
__device__ float4 g_pA[EMAX];   // a0(+PADX), da, b0(+PADY), db
__device__ float4 g_pB[EMAX];   // z0, dz, scale, bits(i_lo | i_hi<<8 | steep<<31)

__global__ void prep_kernel(const float* __restrict__ img,
               const float* __restrict__ tof,
               const float* __restrict__ x1l, const float* __restrict__ y1l,
               const float* __restrict__ x1r, const float* __restrict__ y1r,
               const float* __restrict__ x2l, const float* __restrict__ y2l,
               const float* __restrict__ x2r, const float* __restrict__ y2r,
               const float* __restrict__ trp,
               const float* __restrict__ dxp, const float* __restrict__ dyp,
               const int* __restrict__ nxp, const int* __restrict__ nyp,
               int E)
{
    // Let the dependent (project) grid launch while this kernel runs; its
    // griddepcontrol.wait releases when this grid completes.
    asm volatile("griddepcontrol.launch_dependents;");

    const int nx = *nxp;
    const int ny = *nyp;
    const int tid = threadIdx.x;
    const int blk = blockIdx.x;
    const int NTILES = NTILE * NTILE;

    if (blk < NTILES) {
        // ---- image-tile block: build BOTH layouts from one smem tile ----
        __shared__ float sm[17][18];
        const int ty = blk / NTILE;
        const int tx = blk - ty * NTILE;
        const int ixs = -1 + tx * 16;          // tile origin in image coords
        const int iys = -1 + ty * 16;

        for (int k = tid; k < 17 * 17; k += 256) {
            const int r = k / 17;
            const int c = k - r * 17;
            const int y = iys + r;
            const int x = ixs + c;
            sm[r][c] = (x >= 0 && x < nx && y >= 0 && y < ny)
                       ? img[y * nx + x] : 0.0f;
        }
        __syncthreads();

        // Row-major output: fast axis = x (coalesced 8B stores).
        {
            const int ly = tid >> 4;           // 0..15
            const int lx = tid & 15;
            h4 o;
            o.lo = __floats2half2_rn(sm[ly][lx],     sm[ly + 1][lx]);
            o.hi = __floats2half2_rn(sm[ly][lx + 1], sm[ly + 1][lx + 1]);
            g_padh[(iys + ly + PADY) * PAD_W + (ixs + lx + PADX)] = o;
        }
        // Transposed output: fast axis = y (coalesced 8B stores).
        {
            const int lx = tid >> 4;           // slow: x
            const int ly = tid & 15;           // fast: y
            h4 o;                               // (u,v) = (y,x)
            o.lo = __floats2half2_rn(sm[ly][lx],     sm[ly][lx + 1]);
            o.hi = __floats2half2_rn(sm[ly + 1][lx], sm[ly + 1][lx + 1]);
            g_padhT[(ixs + lx + PADX) * PAD_W + (iys + ly + PADY)] = o;
        }
        return;
    }

    // ---- event block: per-event parameter precompute ----
    const int e = (blk - NTILES) * 256 + tid;
    if (e >= E) return;

    const float dx = *dxp;
    const float dy = *dyp;
    const float nxf = (float)nx;
    const float nyf = (float)ny;

    const float p1x = 0.5f * (x1l[e] + x1r[e]);
    const float p1y = 0.5f * (y1l[e] + y1r[e]);
    const float p2x = 0.5f * (x2l[e] + x2r[e]);
    const float p2y = 0.5f * (y2l[e] + y2r[e]);
    const float dvx = p2x - p1x;
    const float dvy = p2y - p1y;
    const float L   = sqrtf(dvx * dvx + dvy * dvy);

    const float sigma     = (*trp) * 0.3f / (2.0f * 2.3548200450309493f);
    const float inv_sigma = 1.0f / sigma;
    const float norm      = 0.3989422804014327f * inv_sigma;
    const float tc        = 0.5f * L + 0.5f * tof[e];
    const float step      = L * INV_NSAMP;

    const float dfx = dvx * INV_NSAMP / dx;
    const float dfy = dvy * INV_NSAMP / dy;
    const float fx0 = (p1x + dvx * (0.5f * INV_NSAMP)) / dx + 0.5f * nxf - 0.5f;
    const float fy0 = (p1y + dvy * (0.5f * INV_NSAMP)) / dy + 0.5f * nyf - 0.5f;
    const float dz  = step * inv_sigma;          // > 0 (L > 0)
    const float z0  = (step * 0.5f - tc) * inv_sigma;

    int i_lo = (int)floorf((-ZCUT - z0) / dz);
    int i_hi = (int)ceilf (( ZCUT - z0) / dz);
    if (i_lo < 0)         i_lo = 0;
    if (i_lo > NSAMP - 1) i_lo = NSAMP - 1;
    if (i_hi < 0)         i_hi = 0;
    if (i_hi > NSAMP - 1) i_hi = NSAMP - 1;

    const bool steep = fabsf(dvy) > fabsf(dvx);
    const float a0 = (steep ? fy0 : fx0) + (float)PADX;
    const float da = steep ? dfy : dfx;
    const float b0 = (steep ? fx0 : fy0) + (float)PADY;
    const float db = steep ? dfx : dfy;

    unsigned packed = (unsigned)i_lo | ((unsigned)i_hi << 8) |
                      (steep ? 0x80000000u : 0u);

    g_pA[e] = make_float4(a0, da, b0, db);
    g_pB[e] = make_float4(z0, dz, norm * step, __uint_as_float(packed));
}

__global__ void __launch_bounds__(128)
project_kernel(float* __restrict__ out, int E)
{
    // Wait for prep's layout + param stores to be visible.
    asm volatile("griddepcontrol.wait;" ::: "memory");

    const int g = blockIdx.x * blockDim.x + threadIdx.x;
    int       e = g >> 3;                 // event index
    const int h = g & 7;                  // sample phase
    const bool valid = (e < E);
    if (!valid) e = E - 1;

    const float4 pA = g_pA[e];            // a0, da, b0, db
    const float4 pB = g_pB[e];            // z0, dz, scale, packed

    const unsigned packed = __float_as_uint(pB.w);
    const int  i_lo  = (int)(packed & 0xffu);
    const int  i_hi  = (int)((packed >> 8) & 0xffu);
    const bool steep = (packed & 0x80000000u) != 0u;

    const h4* __restrict__ base = steep ? g_padhT : g_padh;

    const float kexp = -0.72134752044448f;     // -0.5 * log2(e)
    const float da = pA.y, db = pA.w;
    const float dz = pB.y;

    // Per-lane initial sample and incremental state (stride 8 in i):
    //   q = kexp * z^2 via second-difference recurrence.
    const int   i0  = i_lo + h;
    const float fi0 = (float)i0;
    float u = fmaf(fi0, da, pA.x);
    float v = fmaf(fi0, db, pA.z);
    const float zs = fmaf(fi0, dz, pB.x);
    const float kd = kexp * dz;
    float q   = (kexp * zs) * zs;
    float dq  = kd * fmaf(64.0f, dz, 16.0f * zs);   // kexp*(16*dz*zs + 64*dz^2)
    const float ddq = 128.0f * kd * dz;
    const float du = 8.0f * da;
    const float dv = 8.0f * db;

    const int n = (i_hi - i0 >= 0) ? ((i_hi - i0) >> 3) + 1 : 0;

    float acc = 0.0f;

    #pragma unroll 4
    for (int it = 0; it < n; ++it) {
        const int iu = (int)u;            // u,v > 0: trunc == floor
        const int iv = (int)v;
        const float wu = u - (float)iu;
        const float wv = v - (float)iv;

        const h4 c = base[iv * PAD_W + iu];

        const __half2 wu2 = __floats2half2_rn(wu, wu);
        const __half2 l2  = __hfma2(wu2, __hsub2(c.hi, c.lo), c.lo);

        const float l0 = __low2float(l2);
        const float l1 = __high2float(l2);
        const float val = fmaf(wv, l1 - l0, l0);

        float w;
        asm("ex2.approx.ftz.f32 %0, %1;" : "=f"(w) : "f"(q));
        acc = fmaf(w, val, acc);

        u += du; v += dv;
        q += dq; dq += ddq;
    }

    acc += __shfl_xor_sync(0xffffffffu, acc, 1);
    acc += __shfl_xor_sync(0xffffffffu, acc, 2);
    acc += __shfl_xor_sync(0xffffffffu, acc, 4);

    if (valid && h == 0)
        out[e] = acc * pB.z;
}

extern "C" void kernel_launch(void* const* d_in, const int* in_sizes, int n_in,
                              void* d_out, int out_size)
{
    const float* image = (const float*)d_in[0];
    const float* tof   = (const float*)d_in[1];
    const float* x1l   = (const float*)d_in[2];
    const float* y1l   = (const float*)d_in[3];
    const float* x1r   = (const float*)d_in[4];
    const float* y1r   = (const float*)d_in[5];
    const float* x2l   = (const float*)d_in[6];
    const float* y2l   = (const float*)d_in[7];
    const float* x2r   = (const float*)d_in[8];
    const float* y2r   = (const float*)d_in[9];
    const float* trp   = (const float*)d_in[10];
    const float* dxp   = (const float*)d_in[11];
    const float* dyp   = (const float*)d_in[12];
    const int*   nxp   = (const int*)d_in[13];
    const int*   nyp   = (const int*)d_in[14];

    const int E = in_sizes[1];

    const int tile_blocks  = NTILE * NTILE;
    const int event_blocks = (E + 255) / 256;
    prep_kernel<<<tile_blocks + event_blocks, 256>>>(image, tof,
                                                     x1l, y1l, x1r, y1r,
                                                     x2l, y2l, x2r, y2r,
                                                     trp, dxp, dyp, nxp, nyp, E);

    const int threads = 128;
    const long long total = (long long)E * SPLIT;
    const int blocks = (int)((total + threads - 1) / threads);

    // Launch project as a PDL secondary on the same (capture) stream.
    cudaLaunchConfig_t cfg = {};
    cfg.gridDim  = dim3((unsigned)blocks, 1, 1);
    cfg.blockDim = dim3((unsigned)threads, 1, 1);
    cfg.dynamicSmemBytes = 0;
    cfg.stream = 0;

    cudaLaunchAttribute attr[1];
    attr[0].id = cudaLaunchAttributeProgrammaticStreamSerialization;
    attr[0].val.programmaticStreamSerializationAllowed = 1;
    cfg.attrs = attr;
    cfg.numAttrs = 1;

    cudaLaunchKernelEx(&cfg, project_kernel, (float*)d_out, E);
}